// round 1
// baseline (speedup 1.0000x reference)
#include <cuda_runtime.h>
#include <cuda_bf16.h>

// IntegrableMLP forward-mode Jacobian.
// inputs [B,2], layers 2->32->32->16 (swish), alpha Jacobian [B,2,width],
// out[b,n] = sum_o V[o] * alpha2[b,n,o].  Output float32 [B,2].
//
// Input order (metadata): inputs, W0, b0, W1, b1, W2, b2, V

#define H0 32
#define H1 32
#define H2 16

__device__ __forceinline__ float fast_sigmoid(float z) {
    return 1.0f / (1.0f + __expf(-z));
}

__global__ __launch_bounds__(256)
void integrable_mlp_kernel(
    const float* __restrict__ x,
    const float* __restrict__ gW0, const float* __restrict__ gb0,
    const float* __restrict__ gW1, const float* __restrict__ gb1,
    const float* __restrict__ gW2, const float* __restrict__ gb2,
    const float* __restrict__ gV,
    float* __restrict__ out, int B)
{
    // Stage all weights in shared memory (~6.8 KB)
    __shared__ float sW0[H0 * 2];
    __shared__ float sb0[H0];
    __shared__ float sW1[H1 * H0];
    __shared__ float sb1[H1];
    __shared__ float sW2[H2 * H1];
    __shared__ float sb2[H2];
    __shared__ float sV[H2];

    for (int i = threadIdx.x; i < H0 * 2; i += blockDim.x) sW0[i] = gW0[i];
    for (int i = threadIdx.x; i < H0;     i += blockDim.x) sb0[i] = gb0[i];
    for (int i = threadIdx.x; i < H1 * H0; i += blockDim.x) sW1[i] = gW1[i];
    for (int i = threadIdx.x; i < H1;     i += blockDim.x) sb1[i] = gb1[i];
    for (int i = threadIdx.x; i < H2 * H1; i += blockDim.x) sW2[i] = gW2[i];
    for (int i = threadIdx.x; i < H2;     i += blockDim.x) sb2[i] = gb2[i];
    for (int i = threadIdx.x; i < H2;     i += blockDim.x) sV[i]  = gV[i];
    __syncthreads();

    int idx = blockIdx.x * blockDim.x + threadIdx.x;
    if (idx >= B) return;

    const float x0 = x[2 * idx];
    const float x1 = x[2 * idx + 1];

    // ---- Layer 0: 2 -> 32.  alpha starts as identity, so beta = W0 columns.
    float a[H0], al0[H0], al1[H0];
#pragma unroll
    for (int o = 0; o < H0; o++) {
        float w0 = sW0[o * 2];
        float w1 = sW0[o * 2 + 1];
        float z = fmaf(w0, x0, fmaf(w1, x1, sb0[o]));
        float s = fast_sigmoid(z);
        float sw = z * s;
        float d = sw + s * (1.0f - sw);   // dswish
        a[o]   = sw;
        al0[o] = d * w0;
        al1[o] = d * w1;
    }

    // ---- Layer 1: 32 -> 32
    float na[H1], n0[H1], n1[H1];
#pragma unroll
    for (int o = 0; o < H1; o++) {
        float z  = sb1[o];
        float t0 = 0.0f;
        float t1 = 0.0f;
#pragma unroll
        for (int i = 0; i < H0; i++) {
            float w = sW1[o * H0 + i];
            z  = fmaf(w, a[i],   z);
            t0 = fmaf(w, al0[i], t0);
            t1 = fmaf(w, al1[i], t1);
        }
        float s = fast_sigmoid(z);
        float sw = z * s;
        float d = sw + s * (1.0f - sw);
        na[o] = sw;
        n0[o] = d * t0;
        n1[o] = d * t1;
    }

    // ---- Layer 2: 32 -> 16, fused with the final V contraction
    float out0 = 0.0f;
    float out1 = 0.0f;
#pragma unroll
    for (int o = 0; o < H2; o++) {
        float z  = sb2[o];
        float t0 = 0.0f;
        float t1 = 0.0f;
#pragma unroll
        for (int i = 0; i < H1; i++) {
            float w = sW2[o * H1 + i];
            z  = fmaf(w, na[i], z);
            t0 = fmaf(w, n0[i], t0);
            t1 = fmaf(w, n1[i], t1);
        }
        float s = fast_sigmoid(z);
        float sw = z * s;
        float d = sw + s * (1.0f - sw);
        float vd = sV[o] * d;
        out0 = fmaf(vd, t0, out0);
        out1 = fmaf(vd, t1, out1);
    }

    out[2 * idx]     = out0;
    out[2 * idx + 1] = out1;
}

extern "C" void kernel_launch(void* const* d_in, const int* in_sizes, int n_in,
                              void* d_out, int out_size) {
    const float* x  = (const float*)d_in[0];
    const float* W0 = (const float*)d_in[1];
    const float* b0 = (const float*)d_in[2];
    const float* W1 = (const float*)d_in[3];
    const float* b1 = (const float*)d_in[4];
    const float* W2 = (const float*)d_in[5];
    const float* b2 = (const float*)d_in[6];
    const float* V  = (const float*)d_in[7];
    float* out = (float*)d_out;

    int B = in_sizes[0] / 2;
    int threads = 256;
    int blocks = (B + threads - 1) / threads;
    integrable_mlp_kernel<<<blocks, threads>>>(x, W0, b0, W1, b1, W2, b2, V, out, B);
}

// round 2
// speedup vs baseline: 1.0657x; 1.0657x over previous
#include <cuda_runtime.h>

// IntegrableMLP forward-mode Jacobian, register-lean phased version.
// inputs [B,2], layers 2->32->32->16 (swish), out[b,n] = V . alpha2[b,n,:].
// Input order: inputs, W0, b0, W1, b1, W2, b2, V.  Output float32 [B,2].

#define H0 32
#define H1 32
#define H2 16
#define BLOCK 256

typedef unsigned long long ull;

struct Smem {
    ull   W1d[H1 * H0];      // duplicated (w,w) pairs for f32x2 FMA
    ull   W2d[H2 * H1];
    float2 W0p[H0];          // (W0[i,0], W0[i,1])
    float W1[H1 * H0];       // scalar copies for z-chain
    float W2[H2 * H1];
    float b0[H0], b1[H1], b2[H2], V[H2];
    float d0s[H0 * BLOCK];   // per-thread scratch: dswish(z0)
    float nas[H1 * BLOCK];   // per-thread scratch: swish(z1)
};

__device__ __forceinline__ ull dupf(float w) {
    unsigned u = __float_as_uint(w);
    return ((ull)u << 32) | (ull)u;
}
__device__ __forceinline__ ull packf2(float lo, float hi) {
    ull r;
    asm("mov.b64 %0, {%1, %2};" : "=l"(r)
        : "r"(__float_as_uint(lo)), "r"(__float_as_uint(hi)));
    return r;
}
__device__ __forceinline__ void unpackf2(ull p, float& lo, float& hi) {
    unsigned a, b;
    asm("mov.b64 {%0, %1}, %2;" : "=r"(a), "=r"(b) : "l"(p));
    lo = __uint_as_float(a);
    hi = __uint_as_float(b);
}
__device__ __forceinline__ ull ffma2(ull a, ull b, ull c) {
    ull d;
    asm("fma.rn.f32x2 %0, %1, %2, %3;" : "=l"(d) : "l"(a), "l"(b), "l"(c));
    return d;
}
__device__ __forceinline__ ull fmul2(ull a, ull b) {
    ull d;
    asm("mul.rn.f32x2 %0, %1, %2;" : "=l"(d) : "l"(a), "l"(b));
    return d;
}
__device__ __forceinline__ float fast_sigmoid(float z) {
    return 1.0f / (1.0f + __expf(-z));
}

__global__ __launch_bounds__(BLOCK, 2)
void integrable_mlp_kernel(
    const float2* __restrict__ x,
    const float* __restrict__ gW0, const float* __restrict__ gb0,
    const float* __restrict__ gW1, const float* __restrict__ gb1,
    const float* __restrict__ gW2, const float* __restrict__ gb2,
    const float* __restrict__ gV,
    float2* __restrict__ out, int B)
{
    extern __shared__ char smem_raw[];
    Smem& sm = *reinterpret_cast<Smem*>(smem_raw);
    const int tid = threadIdx.x;

    // ---- Stage weights (+ duplicated pairs) into shared
    for (int j = tid; j < H1 * H0; j += BLOCK) {
        float w = gW1[j];
        sm.W1[j] = w;
        sm.W1d[j] = dupf(w);
    }
    for (int j = tid; j < H2 * H1; j += BLOCK) {
        float w = gW2[j];
        sm.W2[j] = w;
        sm.W2d[j] = dupf(w);
    }
    if (tid < H0) {
        sm.W0p[tid] = reinterpret_cast<const float2*>(gW0)[tid];
        sm.b0[tid] = gb0[tid];
        sm.b1[tid] = gb1[tid];
    }
    if (tid < H2) {
        sm.b2[tid] = gb2[tid];
        sm.V[tid] = gV[tid];
    }
    __syncthreads();

    const int idx = blockIdx.x * BLOCK + tid;
    if (idx >= B) return;
    const float2 xin = x[idx];

    // ---- Layer 0: 2 -> 32.  Keep a[] in regs, spill d0 to shared scratch.
    float a[H0];
#pragma unroll
    for (int i = 0; i < H0; i++) {
        float2 w = sm.W0p[i];
        float z = fmaf(w.x, xin.x, fmaf(w.y, xin.y, sm.b0[i]));
        float s = fast_sigmoid(z);
        float sw = z * s;
        a[i] = sw;
        sm.d0s[i * BLOCK + tid] = fmaf(s, 1.0f - sw, sw);  // dswish
    }

    // ---- Layer 1 phase 1: z-chain 32 -> 32.  na -> shared, d1 -> regs.
    float d1[H1];
#pragma unroll
    for (int o = 0; o < H1; o++) {
        float z = sm.b1[o];
#pragma unroll
        for (int i = 0; i < H0; i++)
            z = fmaf(sm.W1[o * H0 + i], a[i], z);
        float s = fast_sigmoid(z);
        float sw = z * s;
        sm.nas[o * BLOCK + tid] = sw;
        d1[o] = fmaf(s, 1.0f - sw, sw);
    }

    // ---- Layer 1 phase 2: Jacobian rows, packed f32x2.
    // al01_i = d0_i * (W0[i,0], W0[i,1]) recomputed on the fly.
    ull n01[H1];
#pragma unroll
    for (int o = 0; o < H1; o++) n01[o] = 0ull;
#pragma unroll
    for (int i = 0; i < H0; i++) {
        float d0i = sm.d0s[i * BLOCK + tid];
        float2 w0 = sm.W0p[i];
        ull alp = packf2(d0i * w0.x, d0i * w0.y);
#pragma unroll
        for (int o = 0; o < H1; o++)
            n01[o] = ffma2(sm.W1d[o * H0 + i], alp, n01[o]);
    }
#pragma unroll
    for (int o = 0; o < H1; o++)
        n01[o] = fmul2(n01[o], packf2(d1[o], d1[o]));

    // ---- Layer 2 phase 1: z-chain 32 -> 16, na streamed from shared.
    float z2[H2];
#pragma unroll
    for (int o = 0; o < H2; o++) z2[o] = sm.b2[o];
#pragma unroll
    for (int i = 0; i < H1; i++) {
        float nai = sm.nas[i * BLOCK + tid];
#pragma unroll
        for (int o = 0; o < H2; o++)
            z2[o] = fmaf(sm.W2[o * H1 + i], nai, z2[o]);
    }

    // ---- Layer 2 phase 2: Jacobian + V contraction, packed.
    ull out01 = 0ull;
#pragma unroll
    for (int o = 0; o < H2; o++) {
        float z = z2[o];
        float s = fast_sigmoid(z);
        float sw = z * s;
        float d = fmaf(s, 1.0f - sw, sw);
        float vd = sm.V[o] * d;
        ull t01 = 0ull;
#pragma unroll
        for (int i = 0; i < H1; i++)
            t01 = ffma2(sm.W2d[o * H1 + i], n01[i], t01);
        out01 = ffma2(packf2(vd, vd), t01, out01);
    }

    float o0, o1;
    unpackf2(out01, o0, o1);
    out[idx] = make_float2(o0, o1);
}

extern "C" void kernel_launch(void* const* d_in, const int* in_sizes, int n_in,
                              void* d_out, int out_size) {
    const float2* x = (const float2*)d_in[0];
    const float* W0 = (const float*)d_in[1];
    const float* b0 = (const float*)d_in[2];
    const float* W1 = (const float*)d_in[3];
    const float* b1 = (const float*)d_in[4];
    const float* W2 = (const float*)d_in[5];
    const float* b2 = (const float*)d_in[6];
    const float* V  = (const float*)d_in[7];
    float2* out = (float2*)d_out;

    int B = in_sizes[0] / 2;
    int blocks = (B + BLOCK - 1) / BLOCK;
    size_t shmem = sizeof(Smem);

    static bool attr_set = false;
    if (!attr_set) {
        cudaFuncSetAttribute(integrable_mlp_kernel,
                             cudaFuncAttributeMaxDynamicSharedMemorySize,
                             (int)shmem);
        attr_set = true;
    }
    integrable_mlp_kernel<<<blocks, BLOCK, shmem>>>(
        x, W0, b0, W1, b1, W2, b2, V, out, B);
}